// round 3
// baseline (speedup 1.0000x reference)
#include <cuda_runtime.h>

#define NB   16
#define HH   56
#define HW   3136
#define DIMC 256
#define NQKV 192
#define NMID 64
#define SCALE_F 0.17677669529663688f

// Scratch (static __device__ arrays — allocation-free per harness rules)
static __device__ float g_f[NB * HW * NQKV];    // [b][pixel][192] pixel-major
static __device__ float g_mid[NB * HW * NMID];  // [b][pixel][64]  pixel-major
static __device__ float g_wT[DIMC * NQKV];      // qkv_w transposed [k][n]
static __device__ float g_pT[NMID * DIMC];      // proj_w transposed [k][n]

// ---------------------------------------------------------------------------
// Kernel 0: transpose weights once (tiny)
// ---------------------------------------------------------------------------
__global__ void k_prep(const float* __restrict__ qkv_w,
                       const float* __restrict__ proj_w) {
    int stride = gridDim.x * blockDim.x;
    int i0 = blockIdx.x * blockDim.x + threadIdx.x;
    for (int i = i0; i < DIMC * NQKV; i += stride) {
        int k = i / NQKV, n = i - k * NQKV;
        g_wT[i] = qkv_w[n * DIMC + k];
    }
    for (int i = i0; i < NMID * DIMC; i += stride) {
        int k = i / DIMC, n = i - k * DIMC;
        g_pT[i] = proj_w[n * NMID + k];
    }
}

// ---------------------------------------------------------------------------
// Kernel 1: QKV GEMM.  C[p][n] = sum_k x[b][k][p] * qkv_w[n][k] + qkv_b[n]
// Tile: 64 pixels x 192 outputs, BK=16.  256 threads, 8x6 register tile.
// Output written pixel-major into g_f (coalesced 128B segments).
// ---------------------------------------------------------------------------
__global__ __launch_bounds__(256) void k_qkv(const float* __restrict__ x,
                                             const float* __restrict__ qkv_b) {
    __shared__ float As[16 * 64];
    __shared__ float Bs[16 * 192];
    const int tid = threadIdx.x;
    const int b   = blockIdx.y;
    const int p0  = blockIdx.x * 64;
    const int tn  = tid & 31;   // n lane
    const int tm  = tid >> 5;   // m group (uniform per warp)

    float acc[8][6];
#pragma unroll
    for (int i = 0; i < 8; i++)
#pragma unroll
        for (int j = 0; j < 6; j++) acc[i][j] = 0.f;

    const float* xb = x + (size_t)b * DIMC * HW;

    for (int k0 = 0; k0 < DIMC; k0 += 16) {
#pragma unroll
        for (int r = 0; r < 4; r++) {
            int idx = tid + 256 * r;
            int kk = idx >> 6, m = idx & 63;
            As[kk * 64 + m] = xb[(size_t)(k0 + kk) * HW + p0 + m];
        }
#pragma unroll
        for (int r = 0; r < 12; r++) {
            int idx = tid + 256 * r;
            int kk = idx / 192, n = idx - kk * 192;
            Bs[kk * 192 + n] = g_wT[(k0 + kk) * NQKV + n];
        }
        __syncthreads();
#pragma unroll
        for (int kk = 0; kk < 16; kk++) {
            float a[8], bb[6];
#pragma unroll
            for (int i = 0; i < 8; i++) a[i] = As[kk * 64 + tm + 8 * i];
#pragma unroll
            for (int j = 0; j < 6; j++) bb[j] = Bs[kk * 192 + tn + 32 * j];
#pragma unroll
            for (int i = 0; i < 8; i++)
#pragma unroll
                for (int j = 0; j < 6; j++) acc[i][j] += a[i] * bb[j];
        }
        __syncthreads();
    }

#pragma unroll
    for (int j = 0; j < 6; j++) {
        int n = tn + 32 * j;
        float bias = qkv_b[n];
#pragma unroll
        for (int i = 0; i < 8; i++) {
            g_f[((size_t)b * HW + p0 + tm + 8 * i) * NQKV + n] = acc[i][j] + bias;
        }
    }
}

// ---------------------------------------------------------------------------
// Kernel 2: slide attention.  One thread per (pixel, head).
// Block: 224 threads = 56 x 4 pixel strip for one (b,h); halo in smem planes.
// k[c,idx] = sum_t n_k[t]*Wp[c*9+idx][t] + bias[c*9+idx] (+rpb via qsum trick)
// where Wp = dc1_w + identity (fixed-unfold term folded into the 3x3 matrix).
// ---------------------------------------------------------------------------
__global__ __launch_bounds__(224) void k_attn(const float* __restrict__ dc_b,
                                              const float* __restrict__ dc1_w,
                                              const float* __restrict__ dc1_b,
                                              const float* __restrict__ rpb) {
    __shared__ float sk[8][6][58];
    __shared__ float sv[8][6][58];
    __shared__ float wp[72][9];
    __shared__ float sbias[72];
    __shared__ float srpb[9];

    const int tid  = threadIdx.x;
    const int tile = blockIdx.x;   // 0..13  (rows y0..y0+3)
    const int h    = blockIdx.y;
    const int b    = blockIdx.z;
    const int y0   = tile * 4;

    for (int i = tid; i < 648; i += 224) {
        int o = i / 9, t = i - o * 9;
        wp[o][t] = dc1_w[i] + ((t == (o % 9)) ? 1.0f : 0.0f);
    }
    for (int i = tid; i < 72; i += 224) sbias[i] = dc_b[i] + dc1_b[i];
    if (tid < 9) srpb[tid] = rpb[h * 9 + tid];

    const float* fb = g_f + (size_t)b * HW * NQKV + h * 24;

    // halo tile: 6 rows x 58 cols, zero padded outside image
    for (int i = tid; i < 348; i += 224) {
        int hy = i / 58, hx = i - hy * 58;
        int gy = y0 + hy - 1, gx = hx - 1;
        float4 a0, a1, c0, c1;
        if (gy >= 0 && gy < HH && gx >= 0 && gx < HH) {
            const float* pf = fb + (size_t)(gy * HH + gx) * NQKV;
            a0 = *(const float4*)(pf + 8);
            a1 = *(const float4*)(pf + 12);
            c0 = *(const float4*)(pf + 16);
            c1 = *(const float4*)(pf + 20);
        } else {
            a0 = a1 = c0 = c1 = make_float4(0.f, 0.f, 0.f, 0.f);
        }
        sk[0][hy][hx] = a0.x; sk[1][hy][hx] = a0.y;
        sk[2][hy][hx] = a0.z; sk[3][hy][hx] = a0.w;
        sk[4][hy][hx] = a1.x; sk[5][hy][hx] = a1.y;
        sk[6][hy][hx] = a1.z; sk[7][hy][hx] = a1.w;
        sv[0][hy][hx] = c0.x; sv[1][hy][hx] = c0.y;
        sv[2][hy][hx] = c0.z; sv[3][hy][hx] = c0.w;
        sv[4][hy][hx] = c1.x; sv[5][hy][hx] = c1.y;
        sv[6][hy][hx] = c1.z; sv[7][hy][hx] = c1.w;
    }
    __syncthreads();

    const int ty = tid / 56, tx = tid - ty * 56;
    const int p  = (y0 + ty) * HH + tx;
    const float* pf = fb + (size_t)p * NQKV;
    float4 q0 = *(const float4*)pf;
    float4 q1 = *(const float4*)(pf + 4);
    float q[8] = {q0.x * SCALE_F, q0.y * SCALE_F, q0.z * SCALE_F, q0.w * SCALE_F,
                  q1.x * SCALE_F, q1.y * SCALE_F, q1.z * SCALE_F, q1.w * SCALE_F};
    float qsum = 0.f;
#pragma unroll
    for (int c = 0; c < 8; c++) qsum += q[c];

    float logit[9];
#pragma unroll
    for (int i = 0; i < 9; i++) logit[i] = 0.f;

    // ---- K branch: accumulate logits ----
#pragma unroll
    for (int c = 0; c < 8; c++) {
        float nb[9];
#pragma unroll
        for (int dy = 0; dy < 3; dy++)
#pragma unroll
            for (int dx = 0; dx < 3; dx++)
                nb[dy * 3 + dx] = sk[c][ty + dy][tx + dx];
        float qc = q[c];
#pragma unroll
        for (int idx = 0; idx < 9; idx++) {
            int o = c * 9 + idx;
            float kv = sbias[o];
#pragma unroll
            for (int t = 0; t < 9; t++) kv += nb[t] * wp[o][t];
            logit[idx] += qc * kv;
        }
    }
#pragma unroll
    for (int idx = 0; idx < 9; idx++) logit[idx] += qsum * srpb[idx];

    // ---- softmax over 9 taps ----
    float mx = logit[0];
#pragma unroll
    for (int idx = 1; idx < 9; idx++) mx = fmaxf(mx, logit[idx]);
    float attn[9], s = 0.f;
#pragma unroll
    for (int idx = 0; idx < 9; idx++) {
        attn[idx] = __expf(logit[idx] - mx);
        s += attn[idx];
    }
    float inv = 1.0f / s;
#pragma unroll
    for (int idx = 0; idx < 9; idx++) attn[idx] *= inv;

    // ---- V branch: weighted sum ----
    float ov[8];
#pragma unroll
    for (int c = 0; c < 8; c++) {
        float nb[9];
#pragma unroll
        for (int dy = 0; dy < 3; dy++)
#pragma unroll
            for (int dx = 0; dx < 3; dx++)
                nb[dy * 3 + dx] = sv[c][ty + dy][tx + dx];
        float oc = 0.f;
#pragma unroll
        for (int idx = 0; idx < 9; idx++) {
            int o = c * 9 + idx;
            float vv = sbias[o];
#pragma unroll
            for (int t = 0; t < 9; t++) vv += nb[t] * wp[o][t];
            oc += attn[idx] * vv;
        }
        ov[c] = oc;
    }

    float* po = g_mid + ((size_t)b * HW + p) * NMID + h * 8;
    *(float4*)po       = make_float4(ov[0], ov[1], ov[2], ov[3]);
    *(float4*)(po + 4) = make_float4(ov[4], ov[5], ov[6], ov[7]);
}

// ---------------------------------------------------------------------------
// Kernel 3: proj GEMM.  out[b][n][p] = sum_k mid[b][p][k]*proj_w[n][k]+proj_b[n]
// Tile: 64 pixels x 256 outputs, BK=16.  256 threads, 8x8 register tile.
// Epilogue transposes through padded smem for coalesced NCHW writes.
// ---------------------------------------------------------------------------
__global__ __launch_bounds__(256) void k_proj(const float* __restrict__ proj_b,
                                              float* __restrict__ out) {
    __shared__ float sbuf[128 * 65];  // 33.3KB; aliases As(16x65)+Bs(16x256)
    float* As = sbuf;                 // padded pitch 65
    float* Bs = sbuf + 16 * 65;
    const int tid = threadIdx.x;
    const int b   = blockIdx.y;
    const int p0  = blockIdx.x * 64;
    const int tn  = tid & 31;
    const int tm  = tid >> 5;

    float acc[8][8];
#pragma unroll
    for (int i = 0; i < 8; i++)
#pragma unroll
        for (int j = 0; j < 8; j++) acc[i][j] = 0.f;

    const float* midb = g_mid + (size_t)b * HW * NMID;

    for (int k0 = 0; k0 < NMID; k0 += 16) {
        {
            int m = tid >> 2, kq = (tid & 3) * 4;
            float4 v = *(const float4*)(midb + (size_t)(p0 + m) * NMID + k0 + kq);
            As[(kq + 0) * 65 + m] = v.x;
            As[(kq + 1) * 65 + m] = v.y;
            As[(kq + 2) * 65 + m] = v.z;
            As[(kq + 3) * 65 + m] = v.w;
        }
#pragma unroll
        for (int r = 0; r < 16; r++) {
            int idx = tid + 256 * r;
            int kk = idx >> 8, n = idx & 255;
            Bs[kk * 256 + n] = g_pT[(k0 + kk) * DIMC + n];
        }
        __syncthreads();
#pragma unroll
        for (int kk = 0; kk < 16; kk++) {
            float a[8], bb[8];
#pragma unroll
            for (int i = 0; i < 8; i++) a[i] = As[kk * 65 + tm + 8 * i];
#pragma unroll
            for (int j = 0; j < 8; j++) bb[j] = Bs[kk * 256 + tn + 32 * j];
#pragma unroll
            for (int i = 0; i < 8; i++)
#pragma unroll
                for (int j = 0; j < 8; j++) acc[i][j] += a[i] * bb[j];
        }
        __syncthreads();
    }

    // epilogue in two 128-channel halves through padded smem
    for (int half = 0; half < 2; half++) {
        __syncthreads();
#pragma unroll
        for (int jj = 0; jj < 4; jj++) {
            int j = half * 4 + jj;
            int n = tn + 32 * j;
            float bias = proj_b[n];
            int row = n - half * 128;
#pragma unroll
            for (int i = 0; i < 8; i++)
                sbuf[row * 65 + tm + 8 * i] = acc[i][j] + bias;
        }
        __syncthreads();
#pragma unroll
        for (int r = 0; r < 32; r++) {
            int idx = tid + 256 * r;
            int n = idx >> 6, m = idx & 63;
            out[((size_t)b * DIMC + half * 128 + n) * HW + p0 + m] = sbuf[n * 65 + m];
        }
    }
}

// ---------------------------------------------------------------------------
extern "C" void kernel_launch(void* const* d_in, const int* in_sizes, int n_in,
                              void* d_out, int out_size) {
    const float* x      = (const float*)d_in[0];
    const float* qkv_w  = (const float*)d_in[1];
    const float* qkv_b  = (const float*)d_in[2];
    const float* dc_b   = (const float*)d_in[3];
    const float* dc1_w  = (const float*)d_in[4];
    const float* dc1_b  = (const float*)d_in[5];
    const float* rpb    = (const float*)d_in[6];
    const float* proj_w = (const float*)d_in[7];
    const float* proj_b = (const float*)d_in[8];
    float* out = (float*)d_out;

    k_prep<<<64, 256>>>(qkv_w, proj_w);
    k_qkv<<<dim3(49, NB), 256>>>(x, qkv_b);
    k_attn<<<dim3(14, 8, NB), 224>>>(dc_b, dc1_w, dc1_b, rpb);
    k_proj<<<dim3(49, NB), 256>>>(proj_b, out);
    (void)in_sizes; (void)n_in; (void)out_size;
}